// round 17
// baseline (speedup 1.0000x reference)
#include <cuda_runtime.h>
#include <cuda_fp16.h>
#include <math.h>
#include <cstdint>

// Problem constants
#define BB 2
#define SS 2048
#define EE 2048
#define HH_ 16
#define DD 128
#define E3 (3*EE)

// Scratch (allocation-free rule: __device__ globals)
__device__ __half g_qkvh[(long)BB*SS*E3];   // half qkv (gemm out, rope in-place, FA in)
__device__ __half g_ctxh[(long)BB*SS*EE];   // half ctx (FA out, out-proj in)
__device__ __half g_xh [(long)BB*SS*EE];
__device__ __half g_w1h[(long)E3*EE];
__device__ __half g_w2h[(long)EE*EE];

__device__ __forceinline__ void mma16(float* d, const uint32_t* a, const uint32_t* b) {
    asm volatile("mma.sync.aligned.m16n8k16.row.col.f32.f16.f16.f32 "
        "{%0,%1,%2,%3}, {%4,%5,%6,%7}, {%8,%9}, {%0,%1,%2,%3};"
        : "+f"(d[0]), "+f"(d[1]), "+f"(d[2]), "+f"(d[3])
        : "r"(a[0]), "r"(a[1]), "r"(a[2]), "r"(a[3]), "r"(b[0]), "r"(b[1]));
}
__device__ __forceinline__ void ldsm4(uint32_t* r, uint32_t addr) {
    asm volatile("ldmatrix.sync.aligned.m8n8.x4.shared.b16 {%0,%1,%2,%3}, [%4];"
        : "=r"(r[0]), "=r"(r[1]), "=r"(r[2]), "=r"(r[3]) : "r"(addr));
}
__device__ __forceinline__ void ldsm4t(uint32_t* r, uint32_t addr) {
    asm volatile("ldmatrix.sync.aligned.m8n8.x4.trans.shared.b16 {%0,%1,%2,%3}, [%4];"
        : "=r"(r[0]), "=r"(r[1]), "=r"(r[2]), "=r"(r[3]) : "r"(addr));
}
__device__ __forceinline__ uint32_t smem_u32(const void* p) {
    uint32_t a;
    asm("{ .reg .u64 t; cvta.to.shared.u64 t, %1; cvt.u32.u64 %0, t; }"
        : "=r"(a) : "l"(p));
    return a;
}
__device__ __forceinline__ uint32_t h2pack(float lo, float hi) {
    __half2 h = __floats2half2_rn(lo, hi);
    return *(uint32_t*)&h;
}
__device__ __forceinline__ float ex2(float x) {
    float r; asm("ex2.approx.ftz.f32 %0, %1;" : "=f"(r) : "f"(x)); return r;
}
#define CP_ASYNC16(dst, src) \
    asm volatile("cp.async.ca.shared.global [%0], [%1], 16;" :: "r"(dst), "l"(src))
#define CP_COMMIT() asm volatile("cp.async.commit_group;" ::: "memory")
#define CP_WAIT(n)  asm volatile("cp.async.wait_group %0;" :: "n"(n) : "memory")

// ---------------------------------------------------------------------------
// Fused fp32 -> fp16 round-copy of x, wqkv_w, out_w (one launch).
// ---------------------------------------------------------------------------
__global__ __launch_bounds__(256)
void h16copy3_k(const float* __restrict__ x,  __half* __restrict__ xh,
                const float* __restrict__ w1, __half* __restrict__ w1h,
                const float* __restrict__ w2, __half* __restrict__ w2h)
{
    const float* in; __half* out; long base;
    int bid = blockIdx.x;
    if (bid < 4096)        { in = x;  out = xh;  base = (long)bid * 2048; }
    else if (bid < 10240)  { in = w1; out = w1h; base = (long)(bid - 4096) * 2048; }
    else                   { in = w2; out = w2h; base = (long)(bid - 10240) * 2048; }

    long i = base + (long)threadIdx.x * 8;
    float4 v0 = *(const float4*)(in + i);
    float4 v1 = *(const float4*)(in + i + 4);
    __half2 h0 = __floats2half2_rn(v0.x, v0.y);
    __half2 h1 = __floats2half2_rn(v0.z, v0.w);
    __half2 h2 = __floats2half2_rn(v1.x, v1.y);
    __half2 h3 = __floats2half2_rn(v1.z, v1.w);
    uint4 o;
    o.x = *(uint32_t*)&h0; o.y = *(uint32_t*)&h1;
    o.z = *(uint32_t*)&h2; o.w = *(uint32_t*)&h3;
    *(uint4*)(out + i) = o;
}

// ===========================================================================
// fp16 pipelined GEMM (TRANSB): C[m,n]= sum_k A[m,k]*B[n,k] (+bias)
// CTA 128xBN (BN=192 QKV; BN=256 out-proj), 8 warps (2x4), BK=64, 3-stage.
// ===========================================================================
#define BM2 128
#define BKH 64
#define LDH 72

template<int BN, bool BIAS, bool QKVMODE>
__global__ __launch_bounds__(256)
void tgemm2h(const __half* __restrict__ gA, const __half* __restrict__ gB,
             float* __restrict__ gC, __half* __restrict__ gCh,
             const float* __restrict__ bias,
             int K, int lda, int ldb, int ldc)
{
    constexpr int NP   = BN / 64;
    constexpr int NT   = BN / 32;
    constexpr int A_ST = 128 * LDH;
    constexpr int B_ST = BN * LDH;
    constexpr int STH  = A_ST + B_ST;

    extern __shared__ __half smh[];
    int m0 = blockIdx.y * BM2;
    int n0 = blockIdx.x * BN;
    int niter = K / BKH;

    int tid  = threadIdx.x;
    int wid  = tid >> 5;
    int lane = tid & 31;
    int wm = wid & 1;
    int wn = wid >> 1;
    int gq = lane >> 2;
    int tg = lane & 3;

    int a_row = (lane & 7) + ((lane >> 3) & 1) * 8;
    int a_col = (lane >> 4) * 8;
    int b_row = (lane & 7) + (lane >> 4) * 8;
    int b_col = ((lane >> 3) & 1) * 8;
    uint32_t smbase = smem_u32(smh);
    uint32_t aoff = ((wm*64 + a_row) * LDH + a_col) * 2;
    uint32_t boff = (uint32_t)(A_ST*2) + ((wn*(BN/4) + b_row) * LDH + b_col) * 2;

    float acc[4][NT][4];
    #pragma unroll
    for (int mt = 0; mt < 4; mt++)
        #pragma unroll
        for (int nt = 0; nt < NT; nt++)
            #pragma unroll
            for (int r = 0; r < 4; r++) acc[mt][nt][r] = 0.f;

    auto issue = [&](int it) {
        int k0 = it * BKH;
        __half* As = smh + (it % 3) * STH;
        __half* Bs = As + A_ST;
        const __half* Ab = gA + (long)m0 * lda + k0;
        #pragma unroll
        for (int p = 0; p < 4; p++) {
            int idx = p * 256 + tid;
            int r = idx >> 3, c8 = (idx & 7) << 3;
            CP_ASYNC16(smem_u32(As + r * LDH + c8), Ab + (long)r * lda + c8);
        }
        const __half* Bb = gB + (long)n0 * ldb + k0;
        #pragma unroll
        for (int p = 0; p < BN/32; p++) {
            int idx = p * 256 + tid;
            int r = idx >> 3, c8 = (idx & 7) << 3;
            CP_ASYNC16(smem_u32(Bs + r * LDH + c8), Bb + (long)r * ldb + c8);
        }
        CP_COMMIT();
    };

    auto compute = [&](int s) {
        uint32_t a_base = smbase + s*(STH*2) + aoff;
        uint32_t b_base = smbase + s*(STH*2) + boff;
        #pragma unroll
        for (int ks = 0; ks < 4; ks++) {
            uint32_t kcb = ks * 32;
            uint32_t a[4][4], b[NP][4];
            #pragma unroll
            for (int mt = 0; mt < 4; mt++)
                ldsm4(a[mt], a_base + mt*(16*LDH*2) + kcb);
            #pragma unroll
            for (int np = 0; np < NP; np++)
                ldsm4(b[np], b_base + np*(16*LDH*2) + kcb);
            #pragma unroll
            for (int mt = 0; mt < 4; mt++)
                #pragma unroll
                for (int np = 0; np < NP; np++) {
                    mma16(acc[mt][2*np],   a[mt], &b[np][0]);
                    mma16(acc[mt][2*np+1], a[mt], &b[np][2]);
                }
        }
    };

    issue(0);
    if (niter > 1) issue(1);
    for (int it = 0; it < niter; ++it) {
        if (it + 1 < niter) CP_WAIT(1); else CP_WAIT(0);
        __syncthreads();
        if (it + 2 < niter) issue(it + 2);
        compute(it % 3);
    }

    #pragma unroll
    for (int mt = 0; mt < 4; mt++) {
        int row = m0 + wm*64 + mt*16 + gq;
        #pragma unroll
        for (int nt = 0; nt < NT; nt++) {
            int col = n0 + wn*(BN/4) + nt*8 + 2*tg;
            float b0 = 0.f, b1 = 0.f;
            if (BIAS) { b0 = bias[col]; b1 = bias[col + 1]; }
            float2 v0, v1;
            v0.x = acc[mt][nt][0] + b0; v0.y = acc[mt][nt][1] + b1;
            v1.x = acc[mt][nt][2] + b0; v1.y = acc[mt][nt][3] + b1;
            if (QKVMODE) {
                *(__half2*)(gCh + (long)row * ldc + col)
                    = __floats2half2_rn(v0.x, v0.y);
                *(__half2*)(gCh + (long)(row + 8) * ldc + col)
                    = __floats2half2_rn(v1.x, v1.y);
            } else {
                *(float2*)(gC + (long)row * ldc + col)       = v0;
                *(float2*)(gC + (long)(row + 8) * ldc + col) = v1;
            }
        }
    }
}

// ===========================================================================
// fp16 flash attention, 128-col K-tiles, FA2 ping-pong: PV lags one tile so
// softmax(kt) issues in PV(kt-1)'s tensor shadow. K 2-deep, V 3-deep rings.
// q pre-scaled by 1/sqrt(D)*log2(e) -> softmax via raw ex2.
// Smem: Q | K0 K1 | V0 V1 V2, each 128x136 halves = 208896 bytes
// ===========================================================================
#define FQ_LDH 136
#define FA_TILE_H (128*FQ_LDH)
#define FA_SMEM (6*FA_TILE_H*2)

__global__ __launch_bounds__(256)
void fa_k(const __half* __restrict__ qkv, __half* __restrict__ ctx)
{
    extern __shared__ __half smh[];
    __half* Qs = smh;

    int qt = gridDim.x - 1 - blockIdx.x;       // heavy tiles first
    int bh = blockIdx.y;
    int b = bh >> 4, h = bh & 15;
    const __half* qb = qkv + (long)b*SS*E3 + (long)h*DD;

    int tid = threadIdx.x, wid = tid >> 5, lane = tid & 31;
    int gq = lane >> 2, tg = lane & 3;

    int a_row = (lane & 7) + ((lane >> 3) & 1) * 8;
    int a_col = (lane >> 4) * 8;               // halves
    int b_row = (lane & 7) + (lane >> 4) * 8;
    int b_col = ((lane >> 3) & 1) * 8;
    uint32_t smbase = smem_u32(smh);
    uint32_t qa_base = smbase + ((wid*16 + a_row)*FQ_LDH + a_col) * 2;
    uint32_t kb_off  = (b_row*FQ_LDH + b_col) * 2;
    uint32_t va_off  = (a_row*FQ_LDH + a_col) * 2;

    auto issueKV = [&](int kt) {
        __half* Kd = smh + (1 + (kt & 1)) * FA_TILE_H;
        __half* Vd = smh + (3 + (kt % 3)) * FA_TILE_H;
        const __half* Kg = qb + EE   + (long)(kt*128)*E3;
        const __half* Vg = qb + 2*EE + (long)(kt*128)*E3;
        #pragma unroll
        for (int p = 0; p < 8; p++) {
            int idx = p*256 + tid;
            int r = idx >> 4, c8 = (idx & 15) << 3;
            CP_ASYNC16(smem_u32(Kd + r*FQ_LDH + c8), Kg + (long)r*E3 + c8);
        }
        #pragma unroll
        for (int p = 0; p < 8; p++) {
            int idx = p*256 + tid;
            int r = idx >> 4, c8 = (idx & 15) << 3;
            CP_ASYNC16(smem_u32(Vd + r*FQ_LDH + c8), Vg + (long)r*E3 + c8);
        }
        CP_COMMIT();
    };

    {   // Q tile 128 x 128 halves
        const __half* Qg = qb + (long)(qt*128)*E3;
        #pragma unroll
        for (int p = 0; p < 8; p++) {
            int idx = p*256 + tid;
            int r = idx >> 4, c8 = (idx & 15) << 3;
            CP_ASYNC16(smem_u32(Qs + r*FQ_LDH + c8), Qg + (long)r*E3 + c8);
        }
    }
    issueKV(0);

    float o[16][4];
    #pragma unroll
    for (int nt = 0; nt < 16; nt++)
        #pragma unroll
        for (int r = 0; r < 4; r++) o[nt][r] = 0.f;
    float m0 = -1e30f, m1 = -1e30f, l0 = 0.f, l1 = 0.f;

    int rowg0 = qt*128 + wid*16 + gq;
    int rowg1 = rowg0 + 8;
    int nkt = qt + 1;

    uint32_t phA[32], phB[32];

    // ---- PV: o += P(prev) @ V(ktv) ----
    auto pv = [&](const uint32_t* ph, int ktv) {
        uint32_t vb_base = smbase
            + (uint32_t)((3 + (ktv % 3)) * FA_TILE_H * 2) + va_off;
        #pragma unroll
        for (int ks = 0; ks < 8; ks++) {
            uint32_t v_base = vb_base + (uint32_t)(ks*16*FQ_LDH*2);
            #pragma unroll
            for (int np = 0; np < 8; np++) {
                uint32_t vb[4];
                ldsm4t(vb, v_base + np*32);
                mma16(o[2*np],   &ph[4*ks], &vb[0]);
                mma16(o[2*np+1], &ph[4*ks], &vb[2]);
            }
        }
    };

    // ---- one pipelined iteration: S(kt), PV(kt-1), softmax(kt) ----
    auto step = [&](int kt, uint32_t* cur, const uint32_t* prev) {
        uint32_t kb_base = smbase
            + (uint32_t)((1 + (kt & 1)) * FA_TILE_H * 2) + kb_off;

        float s[16][4];
        #pragma unroll
        for (int nt = 0; nt < 16; nt++)
            #pragma unroll
            for (int r = 0; r < 4; r++) s[nt][r] = 0.f;

        #pragma unroll
        for (int ks = 0; ks < 8; ks++) {       // S = Q K^T
            uint32_t kcb = ks * 32;
            uint32_t a[4];
            ldsm4(a, qa_base + kcb);
            #pragma unroll
            for (int np = 0; np < 8; np++) {
                uint32_t bm[4];
                ldsm4(bm, kb_base + np*(16*FQ_LDH*2) + kcb);
                mma16(s[2*np],   a, &bm[0]);
                mma16(s[2*np+1], a, &bm[2]);
            }
        }

        if (kt > 0) pv(prev, kt - 1);          // deferred PV in S's shadow

        if (kt == qt) {                        // causal mask (diagonal block)
            #pragma unroll
            for (int nt = 0; nt < 16; nt++) {
                int col = kt*128 + nt*8 + 2*tg;
                if (col   > rowg0) s[nt][0] = -1e30f;
                if (col+1 > rowg0) s[nt][1] = -1e30f;
                if (col   > rowg1) s[nt][2] = -1e30f;
                if (col+1 > rowg1) s[nt][3] = -1e30f;
            }
        }

        // online softmax (log2 domain; overlaps in-flight PV)
        float mt0 = -1e30f, mt1 = -1e30f;
        #pragma unroll
        for (int nt = 0; nt < 16; nt++) {
            mt0 = fmaxf(mt0, fmaxf(s[nt][0], s[nt][1]));
            mt1 = fmaxf(mt1, fmaxf(s[nt][2], s[nt][3]));
        }
        mt0 = fmaxf(mt0, __shfl_xor_sync(0xffffffffu, mt0, 1));
        mt0 = fmaxf(mt0, __shfl_xor_sync(0xffffffffu, mt0, 2));
        mt1 = fmaxf(mt1, __shfl_xor_sync(0xffffffffu, mt1, 1));
        mt1 = fmaxf(mt1, __shfl_xor_sync(0xffffffffu, mt1, 2));

        float mn0 = fmaxf(m0, mt0), mn1 = fmaxf(m1, mt1);
        float c0 = ex2(m0 - mn0), c1 = ex2(m1 - mn1);

        float sum0 = 0.f, sum1 = 0.f;
        #pragma unroll
        for (int nt = 0; nt < 16; nt++) {
            float e0 = ex2(s[nt][0] - mn0);
            float e1 = ex2(s[nt][1] - mn0);
            float e2 = ex2(s[nt][2] - mn1);
            float e3 = ex2(s[nt][3] - mn1);
            sum0 += e0 + e1;  sum1 += e2 + e3;
            cur[2*nt]   = h2pack(e0, e1);
            cur[2*nt+1] = h2pack(e2, e3);
        }
        sum0 += __shfl_xor_sync(0xffffffffu, sum0, 1);
        sum0 += __shfl_xor_sync(0xffffffffu, sum0, 2);
        sum1 += __shfl_xor_sync(0xffffffffu, sum1, 1);
        sum1 += __shfl_xor_sync(0xffffffffu, sum1, 2);

        l0 = l0*c0 + sum0;  l1 = l1*c1 + sum1;
        m0 = mn0;           m1 = mn1;

        #pragma unroll
        for (int nt = 0; nt < 16; nt++) {      // waits on PV completion only here
            o[nt][0] *= c0; o[nt][1] *= c0;
            o[nt][2] *= c1; o[nt][3] *= c1;
        }
    };

    for (int kt = 0; kt < nkt; kt++) {
        CP_WAIT(0);
        __syncthreads();                       // K(kt),V(kt) ready
        if (kt + 1 < nkt) issueKV(kt + 1);
        if (kt & 1) step(kt, phB, phA);
        else        step(kt, phA, phB);
    }
    // final deferred PV
    if ((nkt - 1) & 1) pv(phB, nkt - 1);
    else               pv(phA, nkt - 1);

    // ---- normalize + store half ctx ----
    float i0 = 1.f/l0, i1 = 1.f/l1;
    __half* cb0 = ctx + (long)b*SS*EE + (long)rowg0*EE + h*DD;
    __half* cb1 = cb0 + 8*EE;
    #pragma unroll
    for (int nt = 0; nt < 16; nt++) {
        int col = nt*8 + 2*tg;
        __half2 v0 = __floats2half2_rn(o[nt][0]*i0, o[nt][1]*i0);
        __half2 v1 = __floats2half2_rn(o[nt][2]*i1, o[nt][3]*i1);
        *(__half2*)(cb0 + col) = v0;
        *(__half2*)(cb1 + col) = v1;
    }
}

// ---------------------------------------------------------------------------
// RoPE in place on half q,k. q pre-scaled by (1/sqrt(D))*log2(e) so the FA
// softmax can use raw ex2 (base-2 softmax == base-e softmax of scaled logits).
// ---------------------------------------------------------------------------
__global__ __launch_bounds__(256)
void rope_k(__half* __restrict__ qkvh)
{
    long t = (long)blockIdx.x * blockDim.x + threadIdx.x;
    int j = (int)(t & 63);
    int h = (int)((t >> 6) & (HH_-1));
    long bs = t >> 10;
    int s = (int)(bs & (SS-1));

    const float scale = 0.08838834764831845f * 1.4426950408889634f;
    float inv = powf(10000.f, -((float)(2*j)) * (1.f/128.f));
    float fr  = (float)s * inv;
    float c, sn;
    sincosf(fr, &sn, &c);

    __half* qh = qkvh + bs*(long)E3 + (long)h*DD;
    float q1 = __half2float(qh[j]), q2 = __half2float(qh[j+64]);
    qh[j]    = __float2half_rn((q1*c - q2*sn) * scale);
    qh[j+64] = __float2half_rn((q1*sn + q2*c) * scale);

    __half* kh = qh + EE;
    float k1 = __half2float(kh[j]), k2 = __half2float(kh[j+64]);
    kh[j]    = __float2half_rn(k1*c - k2*sn);
    kh[j+64] = __float2half_rn(k1*sn + k2*c);
}

// ---------------------------------------------------------------------------
extern "C" void kernel_launch(void* const* d_in, const int* in_sizes, int n_in,
                              void* d_out, int out_size)
{
    const float* x      = (const float*)d_in[0];
    const float* wqkv_w = (const float*)d_in[1];
    const float* wqkv_b = (const float*)d_in[2];
    const float* out_w  = (const float*)d_in[3];
    const float* out_b  = (const float*)d_in[4];
    float*       out    = (float*)d_out;

    __half *qkvh, *ctxh, *xh, *w1h, *w2h;
    cudaGetSymbolAddress((void**)&qkvh, g_qkvh);
    cudaGetSymbolAddress((void**)&ctxh, g_ctxh);
    cudaGetSymbolAddress((void**)&xh,   g_xh);
    cudaGetSymbolAddress((void**)&w1h,  g_w1h);
    cudaGetSymbolAddress((void**)&w2h,  g_w2h);

    const int SMEM_QKV = 3*(128+192)*LDH*2;   // 138240
    const int SMEM_OUT = 3*(128+256)*LDH*2;   // 165888
    cudaFuncSetAttribute(tgemm2h<192,true,true>,
        cudaFuncAttributeMaxDynamicSharedMemorySize, SMEM_QKV);
    cudaFuncSetAttribute(tgemm2h<256,true,false>,
        cudaFuncAttributeMaxDynamicSharedMemorySize, SMEM_OUT);
    cudaFuncSetAttribute(fa_k,
        cudaFuncAttributeMaxDynamicSharedMemorySize, FA_SMEM);

    const int Mx = BB*SS;             // 4096

    // 0) fused fp16 copies
    h16copy3_k<<<12288, 256>>>(x, xh, wqkv_w, w1h, out_w, w2h);

    // 1) QKV projection: 128x192 tiles -> 1024 CTAs; half output direct
    {
        dim3 g(E3/192, Mx/BM2, 1);
        tgemm2h<192,true,true><<<g,256,SMEM_QKV>>>(
            xh, w1h, nullptr, qkvh, wqkv_b, EE, EE, EE, E3);
    }
    // 2) RoPE in place on half q,k (q pre-scaled incl. log2e)
    {
        long total = (long)BB*SS*HH_*64;
        rope_k<<<(unsigned)(total/256), 256>>>(qkvh);
    }
    // 3) fused flash attention -> half ctx (FA2 ping-pong)
    {
        dim3 g(SS/128, BB*HH_);
        fa_k<<<g,256,FA_SMEM>>>(qkvh, ctxh);
    }
    // 4) output projection (fp16 in, fp32 out + bias)
    {
        dim3 g(EE/256, Mx/BM2, 1);
        tgemm2h<256,true,false><<<g,256,SMEM_OUT>>>(
            ctxh, w2h, out, nullptr, out_b, EE, EE, EE, EE);
    }
}